// round 13
// baseline (speedup 1.0000x reference)
#include <cuda_runtime.h>
#include <cuda_fp16.h>
#include <math.h>
#include <stdint.h>

// Problem constants
#define Bv   4
#define Tv   4096
#define Dv   1024
#define Hv   16
#define HDv  64
#define Cv   128
#define NCv  32            // Tv / Cv
#define Mv   (Bv*Tv)       // 16384

// ---------------------------------------------------------------------------
// Scratch (device globals; no allocation allowed)
// ---------------------------------------------------------------------------
__device__ __align__(16) __half g_Sh[(size_t)Bv * Hv * NCv * HDv * HDv];  // per-chunk S aggregates (fp16)
__device__ __align__(16) float g_z[(size_t)Bv * Hv * NCv * HDv];          // per-chunk z aggregates (fp32)
__device__ int g_flag[Bv * Hv * NCv];                                     // aggregate-ready flags

__device__ __align__(16) __half gA[(size_t)Mv * Dv];   // x (QKV GEMMs), then Y (Wo GEMM)
__device__ __align__(16) __half gW[4 * 1024 * 1024];   // [wsel][K][N] fp16
__device__ __align__(16) __half g_Qh[(size_t)Mv * Dv];
__device__ __align__(16) __half g_Kh[(size_t)Mv * Dv];
__device__ __align__(16) __half g_Vh[(size_t)Mv * Dv];

// ---------------------------------------------------------------------------
// PTX helpers
// ---------------------------------------------------------------------------
__device__ __forceinline__ uint32_t smem_u32(const void* p) {
    uint32_t a;
    asm("{ .reg .u64 t; cvta.to.shared.u64 t, %1; cvt.u32.u64 %0, t; }" : "=r"(a) : "l"(p));
    return a;
}

__device__ __forceinline__ void cp_async16(uint32_t saddr, const void* g) {
    asm volatile("cp.async.cg.shared.global [%0], [%1], 16;" :: "r"(saddr), "l"(g) : "memory");
}

__device__ __forceinline__ void ldsm_x4(uint32_t* r, uint32_t addr) {
    asm volatile("ldmatrix.sync.aligned.m8n8.x4.shared.b16 {%0,%1,%2,%3}, [%4];"
                 : "=r"(r[0]), "=r"(r[1]), "=r"(r[2]), "=r"(r[3]) : "r"(addr));
}
__device__ __forceinline__ void ldsm_x4_t(uint32_t* r, uint32_t addr) {
    asm volatile("ldmatrix.sync.aligned.m8n8.x4.trans.shared.b16 {%0,%1,%2,%3}, [%4];"
                 : "=r"(r[0]), "=r"(r[1]), "=r"(r[2]), "=r"(r[3]) : "r"(addr));
}

__device__ __forceinline__ void mma16816(float* c, const uint32_t* a, uint32_t b0, uint32_t b1) {
    asm volatile(
        "mma.sync.aligned.m16n8k16.row.col.f32.f16.f16.f32 "
        "{%0,%1,%2,%3}, {%4,%5,%6,%7}, {%8,%9}, {%0,%1,%2,%3};"
        : "+f"(c[0]), "+f"(c[1]), "+f"(c[2]), "+f"(c[3])
        : "r"(a[0]), "r"(a[1]), "r"(a[2]), "r"(a[3]), "r"(b0), "r"(b1));
}

__device__ __forceinline__ uint32_t pack_h2(float lo, float hi) {
    __half2 h = __floats2half2_rn(lo, hi);
    return *(uint32_t*)&h;
}

// ---------------------------------------------------------------------------
// Fused fp32 -> fp16 conversion, MLP=4. Block 0 additionally zeroes the
// lookback flags (stream-ordered well before the fused attention kernel).
// ---------------------------------------------------------------------------
#define CONV_A_BLOCKS 4096
#define CONV_W_BLOCKS 1024
#define CONV_BLOCKS   (CONV_A_BLOCKS + CONV_W_BLOCKS)

__global__ __launch_bounds__(256)
void conv_kernel(const float* __restrict__ x,
                 const float* __restrict__ W0, const float* __restrict__ W1,
                 const float* __restrict__ W2, const float* __restrict__ W3)
{
    int blk = blockIdx.x;
    int t   = threadIdx.x;

    if (blk == 0) {
        for (int i = t; i < Bv * Hv * NCv; i += 256) g_flag[i] = 0;
    }

    const float* src;
    unsigned short* dst;
    size_t base_f4;
    if (blk < CONV_A_BLOCKS) {
        src = x;
        dst = (unsigned short*)gA;
        base_f4 = (size_t)blk * 1024;
    } else {
        int wb = blk - CONV_A_BLOCKS;
        int wsel = wb >> 8;
        src = (wsel == 0) ? W0 : (wsel == 1) ? W1 : (wsel == 2) ? W2 : W3;
        dst = (unsigned short*)(gW + ((size_t)wsel << 20));
        base_f4 = (size_t)(wb & 255) * 1024;
    }

    float4 v[4];
#pragma unroll
    for (int k = 0; k < 4; k++)
        v[k] = *(const float4*)(src + (base_f4 + t + (size_t)k * 256) * 4);
#pragma unroll
    for (int k = 0; k < 4; k++) {
        ushort4 h;
        h.x = __half_as_ushort(__float2half_rn(v[k].x));
        h.y = __half_as_ushort(__float2half_rn(v[k].y));
        h.z = __half_as_ushort(__float2half_rn(v[k].z));
        h.w = __half_as_ushort(__float2half_rn(v[k].w));
        *(ushort4*)(dst + (base_f4 + t + (size_t)k * 256) * 4) = h;
    }
}

// ---------------------------------------------------------------------------
// fp16 HMMA GEMM (R9/R11 configuration — at the mma.sync issue floor).
// ---------------------------------------------------------------------------
#define ASTRIDE 40
#define BSTRIDE 136
#define A_SM    (128 * ASTRIDE * 2)      // 10240
#define B_SM    (32 * BSTRIDE * 2)       // 8704
#define STAGE_BYTES (A_SM + B_SM)        // 18944
#define GEMM_SMEM (4 * STAGE_BYTES)      // 75776

__device__ __forceinline__ void gemm_load_stage(
    uint32_t sb, int t, int m0, int n0, int kt,
    const __half* pA, const __half* pB)
{
    int k0 = kt * 32;
#pragma unroll
    for (int it = 0; it < 4; it++) {
        int idx = t + it * 128;
        int row = idx >> 2, c8 = (idx & 3) << 3;
        cp_async16(sb + (uint32_t)(row * ASTRIDE + c8) * 2,
                   pA + (size_t)(m0 + row) * 1024 + k0 + c8);
    }
#pragma unroll
    for (int it = 0; it < 4; it++) {
        int idx = t + it * 128;
        int row = idx >> 4, c8 = (idx & 15) << 3;
        cp_async16(sb + A_SM + (uint32_t)(row * BSTRIDE + c8) * 2,
                   pB + (size_t)(k0 + row) * 1024 + n0 + c8);
    }
    asm volatile("cp.async.commit_group;" ::: "memory");
}

__global__ __launch_bounds__(128, 3)
void mma_gemm_kernel(int wsel, float* __restrict__ Cext, int csel, int fmap)
{
    extern __shared__ __half smh[];
    if (wsel < 0) { wsel = blockIdx.z; csel = blockIdx.z; fmap = (blockIdx.z < 2); }

    const __half* pA = gA;
    const __half* pB = gW + (size_t)wsel * 1024 * 1024;

    int t = threadIdx.x, lane = t & 31, wid = t >> 5;
    int n0 = blockIdx.x * 128;
    int m0 = blockIdx.y * 128;
    uint32_t sbase = smem_u32(smh);

    int wm = (wid >> 1) * 64;
    int wn = (wid & 1) * 64;

    float acc[4][8][4];
#pragma unroll
    for (int mi = 0; mi < 4; mi++)
#pragma unroll
        for (int nt = 0; nt < 8; nt++)
#pragma unroll
            for (int q = 0; q < 4; q++) acc[mi][nt][q] = 0.f;

    gemm_load_stage(sbase, t, m0, n0, 0, pA, pB);
    gemm_load_stage(sbase + STAGE_BYTES, t, m0, n0, 1, pA, pB);
    gemm_load_stage(sbase + 2 * STAGE_BYTES, t, m0, n0, 2, pA, pB);

    for (int kt = 0; kt < 32; kt++) {
        if (kt <= 29)      asm volatile("cp.async.wait_group 2;" ::: "memory");
        else if (kt == 30) asm volatile("cp.async.wait_group 1;" ::: "memory");
        else               asm volatile("cp.async.wait_group 0;" ::: "memory");
        __syncthreads();
        if (kt + 3 < 32)
            gemm_load_stage(sbase + (uint32_t)((kt + 3) & 3) * STAGE_BYTES,
                            t, m0, n0, kt + 3, pA, pB);

        uint32_t sb = sbase + (uint32_t)(kt & 3) * STAGE_BYTES;
#pragma unroll
        for (int ks = 0; ks < 2; ks++) {
            uint32_t aF[4][4], bF[16];
            int arow = lane & 15;
            int acol = ks * 16 + ((lane >> 4) << 3);
#pragma unroll
            for (int mi = 0; mi < 4; mi++)
                ldsm_x4(aF[mi], sb + (uint32_t)((wm + mi * 16 + arow) * ASTRIDE + acol) * 2);

            int brow = ks * 16 + (lane & 15);
#pragma unroll
            for (int p = 0; p < 4; p++) {
                int bcol = wn + p * 16 + ((lane >> 4) << 3);
                ldsm_x4_t(&bF[p * 4], sb + A_SM + (uint32_t)(brow * BSTRIDE + bcol) * 2);
            }
#pragma unroll
            for (int mi = 0; mi < 4; mi++)
#pragma unroll
                for (int nt = 0; nt < 8; nt++)
                    mma16816(acc[mi][nt], aF[mi],
                             bF[(nt >> 1) * 4 + (nt & 1) * 2], bF[(nt >> 1) * 4 + (nt & 1) * 2 + 1]);
        }
    }

    int rbase = m0 + wm + (lane >> 2);
    int cb0 = wn + (lane & 3) * 2;
#pragma unroll
    for (int mi = 0; mi < 4; mi++) {
        int row = rbase + mi * 16;
#pragma unroll
        for (int nt = 0; nt < 8; nt++) {
            float v0 = acc[mi][nt][0], v1 = acc[mi][nt][1];
            float v2 = acc[mi][nt][2], v3 = acc[mi][nt][3];
            if (fmap) {
                v0 = v0 > 0.f ? v0 + 1.f : expf(v0);
                v1 = v1 > 0.f ? v1 + 1.f : expf(v1);
                v2 = v2 > 0.f ? v2 + 1.f : expf(v2);
                v3 = v3 > 0.f ? v3 + 1.f : expf(v3);
            }
            if (csel < 3) {
                __half* Ch = (csel == 0) ? g_Qh : (csel == 1) ? g_Kh : g_Vh;
                *(uint32_t*)((unsigned short*)Ch + (size_t)row * 1024 + n0 + cb0 + nt * 8)
                    = pack_h2(v0, v1);
                *(uint32_t*)((unsigned short*)Ch + (size_t)(row + 8) * 1024 + n0 + cb0 + nt * 8)
                    = pack_h2(v2, v3);
            } else {
                float2 o0; o0.x = v0; o0.y = v1;
                float2 o1; o1.x = v2; o1.y = v3;
                *(float2*)(Cext + (size_t)row * 1024 + n0 + cb0 + nt * 8) = o0;
                *(float2*)(Cext + (size_t)(row + 8) * 1024 + n0 + cb0 + nt * 8) = o1;
            }
        }
    }
}

// ---------------------------------------------------------------------------
// Fused attention (phases A+B+C): per (b,h,chunk) CTA.
//  1. load Q,K,V tiles once
//  2. warps 0-3: S_local = K^T V (HMMA); warps 4-7: z_local = colsum(K)
//  3. publish aggregates (fp16 S, fp32 z) + release flag
//  4. decoupled lookback: sum predececessor aggregates (fp32) -> exclusive prefix
//  5. P = tril(QK^T); den = rowsum(P)+Q·z+eps; O = (P·V + Q·S_prefix)/den -> gA fp16
// blockIdx = bh*32 + c (c fastest) => waits only on strictly-lower blockIdx.
// ---------------------------------------------------------------------------
#define QS_STRIDE 72
#define PHAC_SMEM ((3 * 128 * QS_STRIDE + 64 * QS_STRIDE) * 2 + 64 * 4 + 128 * 4)

__global__ __launch_bounds__(256)
void phaseAC_kernel()
{
    extern __shared__ __half smc[];
    __half* Qs = smc;
    __half* Ks = smc + 128 * QS_STRIDE;
    __half* Vs = smc + 2 * 128 * QS_STRIDE;
    __half* Sh = smc + 3 * 128 * QS_STRIDE;
    float*  zf = (float*)(smc + 3 * 128 * QS_STRIDE + 64 * QS_STRIDE);
    float*  zpart = zf + 64;

    int blk = blockIdx.x;
    int c   = blk & (NCv - 1);
    int bh  = blk >> 5;
    int h   = bh & (Hv - 1);
    int b   = bh >> 4;
    int t   = threadIdx.x;
    int lane = t & 31, wid = t >> 5;

    size_t base = ((size_t)(b * Tv + c * Cv)) * Dv + h * HDv;

    // 1. Load Q/K/V tiles
    for (int idx = t; idx < 128 * 8; idx += 256) {
        int row = idx >> 3, c8 = (idx & 7) << 3;
        size_t go = base + (size_t)row * Dv + c8;
        uint32_t so = (uint32_t)(row * QS_STRIDE + c8);
        *(uint4*)&Qs[so] = *(const uint4*)((const unsigned short*)g_Qh + go);
        *(uint4*)&Ks[so] = *(const uint4*)((const unsigned short*)g_Kh + go);
        *(uint4*)&Vs[so] = *(const uint4*)((const unsigned short*)g_Vh + go);
    }
    __syncthreads();

    uint32_t qsb = smem_u32(Qs), ksb = smem_u32(Ks), vsb = smem_u32(Vs), shb = smem_u32(Sh);

    // 2. S_local (warps 0-3) and z_local (warps 4-7)
    if (wid < 4) {
        int wm = wid * 16;
        float cS[8][4];
#pragma unroll
        for (int nb = 0; nb < 8; nb++)
#pragma unroll
            for (int q = 0; q < 4; q++) cS[nb][q] = 0.f;

        int a_rofs = ((lane >> 4) << 3) + (lane & 7);
        int a_cofs = wm + (((lane >> 3) & 1) << 3);
        int brow = lane & 15, bcol8 = (lane >> 4) << 3;

#pragma unroll
        for (int ks = 0; ks < 8; ks++) {
            uint32_t a[4];
            ldsm_x4_t(a, ksb + (uint32_t)((ks * 16 + a_rofs) * QS_STRIDE + a_cofs) * 2);
#pragma unroll
            for (int p = 0; p < 4; p++) {
                uint32_t r[4];
                ldsm_x4_t(r, vsb + (uint32_t)((ks * 16 + brow) * QS_STRIDE + p * 16 + bcol8) * 2);
                mma16816(cS[2 * p],     a, r[0], r[1]);
                mma16816(cS[2 * p + 1], a, r[2], r[3]);
            }
        }

        unsigned short* Sg = (unsigned short*)g_Sh + (size_t)blk * (HDv * HDv);
        int d0 = wm + (lane >> 2);
        int e0 = (lane & 3) * 2;
#pragma unroll
        for (int nb = 0; nb < 8; nb++) {
            *(uint32_t*)(Sg + d0 * 64 + nb * 8 + e0)       = pack_h2(cS[nb][0], cS[nb][1]);
            *(uint32_t*)(Sg + (d0 + 8) * 64 + nb * 8 + e0) = pack_h2(cS[nb][2], cS[nb][3]);
        }
    } else {
        int t2 = t - 128;                 // 0..127
        int col = t2 & 63, half = t2 >> 6;
        float s = 0.f;
        int r0 = half * 64;
        for (int r = r0; r < r0 + 64; r++) s += __half2float(Ks[r * QS_STRIDE + col]);
        zpart[t2] = s;
    }
    __syncthreads();
    if (t < 64) g_z[(size_t)blk * HDv + t] = zpart[t] + zpart[64 + t];

    // 3. Release flag (all aggregate stores done)
    __threadfence();
    __syncthreads();
    if (t == 0) atomicExch(&g_flag[blk], 1);

    // 4. Decoupled lookback: exclusive prefix over aggregates [0, c)
    float accS[16];
#pragma unroll
    for (int j = 0; j < 16; j++) accS[j] = 0.f;
    float accZ = 0.f;

    for (int cp = 0; cp < c; cp++) {
        int pblk = (bh << 5) + cp;
        if (t == 0) {
            while (atomicAdd(&g_flag[pblk], 0) == 0) { __nanosleep(64); }
        }
        __syncthreads();
        __threadfence();

        const uint4* Ag = (const uint4*)((const unsigned short*)g_Sh
                                         + (size_t)pblk * (HDv * HDv) + t * 16);
        uint4 u0 = __ldcg(Ag);
        uint4 u1 = __ldcg(Ag + 1);
        unsigned short hs[16];
        *(uint4*)(hs)     = u0;
        *(uint4*)(hs + 8) = u1;
#pragma unroll
        for (int j = 0; j < 16; j++)
            accS[j] += __half2float(__ushort_as_half(hs[j]));
        if (t < 64) accZ += __ldcg(&g_z[(size_t)pblk * HDv + t]);
    }

    // Stage prefix into smem
#pragma unroll
    for (int j = 0; j < 16; j++) {
        int idx = t * 16 + j;
        Sh[(idx >> 6) * QS_STRIDE + (idx & 63)] = __float2half_rn(accS[j]);
    }
    if (t < 64) zf[t] = accZ;
    __syncthreads();

    // 5. phaseC math (unchanged)
    int i0 = wid * 16;
    int arow = lane & 15, acol8 = (lane >> 4) << 3;

    uint32_t aQ[4][4];
#pragma unroll
    for (int ks = 0; ks < 4; ks++)
        ldsm_x4(aQ[ks], qsb + (uint32_t)((i0 + arow) * QS_STRIDE + ks * 16 + acol8) * 2);

    float cP[16][4];
#pragma unroll
    for (int nb = 0; nb < 16; nb++)
#pragma unroll
        for (int q = 0; q < 4; q++) cP[nb][q] = 0.f;

#pragma unroll
    for (int ks = 0; ks < 4; ks++) {
#pragma unroll
        for (int jb = 0; jb < 8; jb++) {
            uint32_t r[4];
            ldsm_x4(r, ksb + (uint32_t)((jb * 16 + arow) * QS_STRIDE + ks * 16 + acol8) * 2);
            mma16816(cP[2 * jb],     aQ[ks], r[0], r[2]);
            mma16816(cP[2 * jb + 1], aQ[ks], r[1], r[3]);
        }
    }

    int r0 = i0 + (lane >> 2);
    int cb = (lane & 3) * 2;
    float rs0 = 0.f, rs1 = 0.f;
#pragma unroll
    for (int nb = 0; nb < 16; nb++) {
        int j0 = nb * 8 + cb;
        if (j0     > r0)     cP[nb][0] = 0.f;
        if (j0 + 1 > r0)     cP[nb][1] = 0.f;
        if (j0     > r0 + 8) cP[nb][2] = 0.f;
        if (j0 + 1 > r0 + 8) cP[nb][3] = 0.f;
        rs0 += cP[nb][0] + cP[nb][1];
        rs1 += cP[nb][2] + cP[nb][3];
    }
    rs0 += __shfl_xor_sync(0xffffffffu, rs0, 1);
    rs0 += __shfl_xor_sync(0xffffffffu, rs0, 2);
    rs1 += __shfl_xor_sync(0xffffffffu, rs1, 1);
    rs1 += __shfl_xor_sync(0xffffffffu, rs1, 2);

    float qz0 = 0.f, qz1 = 0.f;
    for (int d = 0; d < 64; d++) {
        float zz = zf[d];
        qz0 += __half2float(Qs[r0 * QS_STRIDE + d]) * zz;
        qz1 += __half2float(Qs[(r0 + 8) * QS_STRIDE + d]) * zz;
    }
    float inv0 = 1.f / (rs0 + qz0 + 1e-6f);
    float inv1 = 1.f / (rs1 + qz1 + 1e-6f);

    uint32_t aP[8][4];
#pragma unroll
    for (int jk = 0; jk < 8; jk++) {
        aP[jk][0] = pack_h2(cP[2 * jk][0],     cP[2 * jk][1]);
        aP[jk][1] = pack_h2(cP[2 * jk][2],     cP[2 * jk][3]);
        aP[jk][2] = pack_h2(cP[2 * jk + 1][0], cP[2 * jk + 1][1]);
        aP[jk][3] = pack_h2(cP[2 * jk + 1][2], cP[2 * jk + 1][3]);
    }

    float cO[8][4];
#pragma unroll
    for (int nb = 0; nb < 8; nb++)
#pragma unroll
        for (int q = 0; q < 4; q++) cO[nb][q] = 0.f;

#pragma unroll
    for (int jk = 0; jk < 8; jk++) {
#pragma unroll
        for (int p = 0; p < 4; p++) {
            uint32_t r[4];
            ldsm_x4_t(r, vsb + (uint32_t)((jk * 16 + arow) * QS_STRIDE + p * 16 + acol8) * 2);
            mma16816(cO[2 * p],     aP[jk], r[0], r[1]);
            mma16816(cO[2 * p + 1], aP[jk], r[2], r[3]);
        }
    }
#pragma unroll
    for (int ks = 0; ks < 4; ks++) {
#pragma unroll
        for (int p = 0; p < 4; p++) {
            uint32_t r[4];
            ldsm_x4_t(r, shb + (uint32_t)((ks * 16 + arow) * QS_STRIDE + p * 16 + acol8) * 2);
            mma16816(cO[2 * p],     aQ[ks], r[0], r[1]);
            mma16816(cO[2 * p + 1], aQ[ks], r[2], r[3]);
        }
    }

    unsigned short* Yg = (unsigned short*)gA + base;
#pragma unroll
    for (int nb = 0; nb < 8; nb++) {
        int e = nb * 8 + cb;
        *(uint32_t*)(Yg + (size_t)r0 * Dv + e)       = pack_h2(cO[nb][0] * inv0, cO[nb][1] * inv0);
        *(uint32_t*)(Yg + (size_t)(r0 + 8) * Dv + e) = pack_h2(cO[nb][2] * inv1, cO[nb][3] * inv1);
    }
}

// ---------------------------------------------------------------------------
// Launch
// ---------------------------------------------------------------------------
extern "C" void kernel_launch(void* const* d_in, const int* in_sizes, int n_in,
                              void* d_out, int out_size)
{
    const float* x  = (const float*)d_in[0];
    const float* Wq = (const float*)d_in[1];
    const float* Wk = (const float*)d_in[2];
    const float* Wv = (const float*)d_in[3];
    const float* Wo = (const float*)d_in[4];
    float* out = (float*)d_out;

    cudaFuncSetAttribute(mma_gemm_kernel,
                         cudaFuncAttributeMaxDynamicSharedMemorySize, GEMM_SMEM);
    cudaFuncSetAttribute(phaseAC_kernel,
                         cudaFuncAttributeMaxDynamicSharedMemorySize, PHAC_SMEM);

    conv_kernel<<<CONV_BLOCKS, 256>>>(x, Wq, Wk, Wv, Wo);   // also zeroes flags

    dim3 gqkv(1024 / 128, Mv / 128, 3);
    mma_gemm_kernel<<<gqkv, 128, GEMM_SMEM>>>(-1, nullptr, 0, 0);  // fp16 Q/K/V

    phaseAC_kernel<<<Bv * Hv * NCv, 256, PHAC_SMEM>>>();           // fused A+B+C -> fp16 Y in gA

    dim3 go(1024 / 128, Mv / 128);
    mma_gemm_kernel<<<go, 128, GEMM_SMEM>>>(3, out, 3, 0);         // out = Y@Wo
}

// round 14
// speedup vs baseline: 1.1742x; 1.1742x over previous
#include <cuda_runtime.h>
#include <cuda_fp16.h>
#include <math.h>
#include <stdint.h>

// Problem constants
#define Bv   4
#define Tv   4096
#define Dv   1024
#define Hv   16
#define HDv  64
#define Cv   128
#define NCv  32            // Tv / Cv
#define Mv   (Bv*Tv)       // 16384

// ---------------------------------------------------------------------------
// Scratch (device globals; no allocation allowed)
// ---------------------------------------------------------------------------
__device__ __align__(16) __half g_Sh[(size_t)Bv * Hv * NCv * HDv * HDv];  // fp16 S states
__device__ __align__(16) float g_z[(size_t)Bv * Hv * NCv * HDv];

__device__ __align__(16) __half gA[(size_t)Mv * Dv];   // x (QKV GEMMs), then Y (Wo GEMM)
__device__ __align__(16) __half gW[4 * 1024 * 1024];   // [wsel][K][N] fp16
__device__ __align__(16) __half g_Qh[(size_t)Mv * Dv];
__device__ __align__(16) __half g_Kh[(size_t)Mv * Dv];
__device__ __align__(16) __half g_Vh[(size_t)Mv * Dv];

// ---------------------------------------------------------------------------
// PTX helpers
// ---------------------------------------------------------------------------
__device__ __forceinline__ uint32_t smem_u32(const void* p) {
    uint32_t a;
    asm("{ .reg .u64 t; cvta.to.shared.u64 t, %1; cvt.u32.u64 %0, t; }" : "=r"(a) : "l"(p));
    return a;
}

__device__ __forceinline__ void cp_async16(uint32_t saddr, const void* g) {
    asm volatile("cp.async.cg.shared.global [%0], [%1], 16;" :: "r"(saddr), "l"(g) : "memory");
}

__device__ __forceinline__ void ldsm_x4(uint32_t* r, uint32_t addr) {
    asm volatile("ldmatrix.sync.aligned.m8n8.x4.shared.b16 {%0,%1,%2,%3}, [%4];"
                 : "=r"(r[0]), "=r"(r[1]), "=r"(r[2]), "=r"(r[3]) : "r"(addr));
}
__device__ __forceinline__ void ldsm_x4_t(uint32_t* r, uint32_t addr) {
    asm volatile("ldmatrix.sync.aligned.m8n8.x4.trans.shared.b16 {%0,%1,%2,%3}, [%4];"
                 : "=r"(r[0]), "=r"(r[1]), "=r"(r[2]), "=r"(r[3]) : "r"(addr));
}

__device__ __forceinline__ void mma16816(float* c, const uint32_t* a, uint32_t b0, uint32_t b1) {
    asm volatile(
        "mma.sync.aligned.m16n8k16.row.col.f32.f16.f16.f32 "
        "{%0,%1,%2,%3}, {%4,%5,%6,%7}, {%8,%9}, {%0,%1,%2,%3};"
        : "+f"(c[0]), "+f"(c[1]), "+f"(c[2]), "+f"(c[3])
        : "r"(a[0]), "r"(a[1]), "r"(a[2]), "r"(a[3]), "r"(b0), "r"(b1));
}

__device__ __forceinline__ uint32_t pack_h2(float lo, float hi) {
    __half2 h = __floats2half2_rn(lo, hi);
    return *(uint32_t*)&h;
}

// ---------------------------------------------------------------------------
// Fused fp32 -> fp16 conversion, MLP=4.
// ---------------------------------------------------------------------------
#define CONV_A_BLOCKS 4096
#define CONV_W_BLOCKS 1024
#define CONV_BLOCKS   (CONV_A_BLOCKS + CONV_W_BLOCKS)

__global__ __launch_bounds__(256)
void conv_kernel(const float* __restrict__ x,
                 const float* __restrict__ W0, const float* __restrict__ W1,
                 const float* __restrict__ W2, const float* __restrict__ W3)
{
    int blk = blockIdx.x;
    int t   = threadIdx.x;
    const float* src;
    unsigned short* dst;
    size_t base_f4;
    if (blk < CONV_A_BLOCKS) {
        src = x;
        dst = (unsigned short*)gA;
        base_f4 = (size_t)blk * 1024;
    } else {
        int wb = blk - CONV_A_BLOCKS;
        int wsel = wb >> 8;
        src = (wsel == 0) ? W0 : (wsel == 1) ? W1 : (wsel == 2) ? W2 : W3;
        dst = (unsigned short*)(gW + ((size_t)wsel << 20));
        base_f4 = (size_t)(wb & 255) * 1024;
    }

    float4 v[4];
#pragma unroll
    for (int k = 0; k < 4; k++)
        v[k] = *(const float4*)(src + (base_f4 + t + (size_t)k * 256) * 4);
#pragma unroll
    for (int k = 0; k < 4; k++) {
        ushort4 h;
        h.x = __half_as_ushort(__float2half_rn(v[k].x));
        h.y = __half_as_ushort(__float2half_rn(v[k].y));
        h.z = __half_as_ushort(__float2half_rn(v[k].z));
        h.w = __half_as_ushort(__float2half_rn(v[k].w));
        *(ushort4*)(dst + (base_f4 + t + (size_t)k * 256) * 4) = h;
    }
}

// ---------------------------------------------------------------------------
// fp16 HMMA GEMM v2: CTA 128x128, BK=32, 4-stage cp.async, 256 threads,
// 8 warps in 2(m) x 4(n) grid with 64x32 warp tiles (acc=64 regs) so
// 2 CTAs/SM = 16 warps/SM hide ldsm->mma latency (tensor pipe was 55% idle
// at 12 warps with the old 64x64 tiles).
// ---------------------------------------------------------------------------
#define ASTRIDE 40
#define BSTRIDE 136
#define A_SM    (128 * ASTRIDE * 2)      // 10240
#define B_SM    (32 * BSTRIDE * 2)       // 8704
#define STAGE_BYTES (A_SM + B_SM)        // 18944
#define GEMM_SMEM (4 * STAGE_BYTES)      // 75776

__device__ __forceinline__ void gemm_load_stage(
    uint32_t sb, int t, int m0, int n0, int kt,
    const __half* pA, const __half* pB)
{
    int k0 = kt * 32;
#pragma unroll
    for (int it = 0; it < 2; it++) {           // A: 128 rows x 32 cols (512 uint4)
        int idx = t + it * 256;
        int row = idx >> 2, c8 = (idx & 3) << 3;
        cp_async16(sb + (uint32_t)(row * ASTRIDE + c8) * 2,
                   pA + (size_t)(m0 + row) * 1024 + k0 + c8);
    }
#pragma unroll
    for (int it = 0; it < 2; it++) {           // B: 32 rows x 128 cols (512 uint4)
        int idx = t + it * 256;
        int row = idx >> 4, c8 = (idx & 15) << 3;
        cp_async16(sb + A_SM + (uint32_t)(row * BSTRIDE + c8) * 2,
                   pB + (size_t)(k0 + row) * 1024 + n0 + c8);
    }
    asm volatile("cp.async.commit_group;" ::: "memory");
}

__global__ __launch_bounds__(256, 2)
void mma_gemm_kernel(int wsel, float* __restrict__ Cext, int csel, int fmap)
{
    extern __shared__ __half smh[];
    if (wsel < 0) { wsel = blockIdx.z; csel = blockIdx.z; fmap = (blockIdx.z < 2); }

    const __half* pA = gA;
    const __half* pB = gW + (size_t)wsel * 1024 * 1024;

    int t = threadIdx.x, lane = t & 31, wid = t >> 5;
    int n0 = blockIdx.x * 128;
    int m0 = blockIdx.y * 128;
    uint32_t sbase = smem_u32(smh);

    int wm = (wid >> 2) * 64;     // 2 m-groups
    int wn = (wid & 3) * 32;      // 4 n-groups

    float acc[4][4][4];           // mi (16-row blocks) x nt (8-col blocks) x 4
#pragma unroll
    for (int mi = 0; mi < 4; mi++)
#pragma unroll
        for (int nt = 0; nt < 4; nt++)
#pragma unroll
            for (int q = 0; q < 4; q++) acc[mi][nt][q] = 0.f;

    gemm_load_stage(sbase, t, m0, n0, 0, pA, pB);
    gemm_load_stage(sbase + STAGE_BYTES, t, m0, n0, 1, pA, pB);
    gemm_load_stage(sbase + 2 * STAGE_BYTES, t, m0, n0, 2, pA, pB);

    for (int kt = 0; kt < 32; kt++) {
        if (kt <= 29)      asm volatile("cp.async.wait_group 2;" ::: "memory");
        else if (kt == 30) asm volatile("cp.async.wait_group 1;" ::: "memory");
        else               asm volatile("cp.async.wait_group 0;" ::: "memory");
        __syncthreads();
        if (kt + 3 < 32)
            gemm_load_stage(sbase + (uint32_t)((kt + 3) & 3) * STAGE_BYTES,
                            t, m0, n0, kt + 3, pA, pB);

        uint32_t sb = sbase + (uint32_t)(kt & 3) * STAGE_BYTES;
#pragma unroll
        for (int ks = 0; ks < 2; ks++) {
            uint32_t aF[4][4], bF[8];
            int arow = lane & 15;
            int acol = ks * 16 + ((lane >> 4) << 3);
#pragma unroll
            for (int mi = 0; mi < 4; mi++)
                ldsm_x4(aF[mi], sb + (uint32_t)((wm + mi * 16 + arow) * ASTRIDE + acol) * 2);

            int brow = ks * 16 + (lane & 15);
#pragma unroll
            for (int p = 0; p < 2; p++) {
                int bcol = wn + p * 16 + ((lane >> 4) << 3);
                ldsm_x4_t(&bF[p * 4], sb + A_SM + (uint32_t)(brow * BSTRIDE + bcol) * 2);
            }
#pragma unroll
            for (int mi = 0; mi < 4; mi++)
#pragma unroll
                for (int nt = 0; nt < 4; nt++)
                    mma16816(acc[mi][nt], aF[mi],
                             bF[(nt >> 1) * 4 + (nt & 1) * 2],
                             bF[(nt >> 1) * 4 + (nt & 1) * 2 + 1]);
        }
    }

    int rbase = m0 + wm + (lane >> 2);
    int cb0 = wn + (lane & 3) * 2;
#pragma unroll
    for (int mi = 0; mi < 4; mi++) {
        int row = rbase + mi * 16;
#pragma unroll
        for (int nt = 0; nt < 4; nt++) {
            float v0 = acc[mi][nt][0], v1 = acc[mi][nt][1];
            float v2 = acc[mi][nt][2], v3 = acc[mi][nt][3];
            if (fmap) {
                v0 = v0 > 0.f ? v0 + 1.f : expf(v0);
                v1 = v1 > 0.f ? v1 + 1.f : expf(v1);
                v2 = v2 > 0.f ? v2 + 1.f : expf(v2);
                v3 = v3 > 0.f ? v3 + 1.f : expf(v3);
            }
            if (csel < 3) {
                __half* Ch = (csel == 0) ? g_Qh : (csel == 1) ? g_Kh : g_Vh;
                *(uint32_t*)((unsigned short*)Ch + (size_t)row * 1024 + n0 + cb0 + nt * 8)
                    = pack_h2(v0, v1);
                *(uint32_t*)((unsigned short*)Ch + (size_t)(row + 8) * 1024 + n0 + cb0 + nt * 8)
                    = pack_h2(v2, v3);
            } else {
                float2 o0; o0.x = v0; o0.y = v1;
                float2 o1; o1.x = v2; o1.y = v3;
                *(float2*)(Cext + (size_t)row * 1024 + n0 + cb0 + nt * 8) = o0;
                *(float2*)(Cext + (size_t)(row + 8) * 1024 + n0 + cb0 + nt * 8) = o1;
            }
        }
    }
}

// ---------------------------------------------------------------------------
// Phase A (tensor): S_c = K_c^T V_c (fp16 out), z_c = col sums of K (fp32).
// ---------------------------------------------------------------------------
#define PA_STRIDE 72

__global__ __launch_bounds__(128)
void phaseA_kernel()
{
    __shared__ __half Ks[128 * PA_STRIDE];
    __shared__ __half Vs[128 * PA_STRIDE];

    int blk = blockIdx.x;
    int c   = blk & (NCv - 1);
    int bh  = blk >> 5;
    int h   = bh & (Hv - 1);
    int b   = bh >> 4;
    int t   = threadIdx.x;
    int lane = t & 31, wid = t >> 5;

    size_t base = ((size_t)(b * Tv + c * Cv)) * Dv + h * HDv;

    for (int idx = t; idx < 128 * 8; idx += 128) {
        int row = idx >> 3, c8 = (idx & 7) << 3;
        size_t go = base + (size_t)row * Dv + c8;
        *(uint4*)&Ks[row * PA_STRIDE + c8] = *(const uint4*)((const unsigned short*)g_Kh + go);
        *(uint4*)&Vs[row * PA_STRIDE + c8] = *(const uint4*)((const unsigned short*)g_Vh + go);
    }
    __syncthreads();

    if (t < 64) {
        float s = 0.f;
        for (int tt = 0; tt < 128; tt++) s += __half2float(Ks[tt * PA_STRIDE + t]);
        g_z[(size_t)(bh * NCv + c) * HDv + t] = s;
    }

    uint32_t ksb = smem_u32(Ks);
    uint32_t vsb = smem_u32(Vs);

    int wm = wid * 16;
    float cS[8][4];
#pragma unroll
    for (int nb = 0; nb < 8; nb++)
#pragma unroll
        for (int q = 0; q < 4; q++) cS[nb][q] = 0.f;

    int a_rofs = ((lane >> 4) << 3) + (lane & 7);
    int a_cofs = wm + (((lane >> 3) & 1) << 3);
    int brow = lane & 15, bcol8 = (lane >> 4) << 3;

#pragma unroll
    for (int ks = 0; ks < 8; ks++) {
        uint32_t a[4];
        ldsm_x4_t(a, ksb + (uint32_t)((ks * 16 + a_rofs) * PA_STRIDE + a_cofs) * 2);
#pragma unroll
        for (int p = 0; p < 4; p++) {
            uint32_t r[4];
            ldsm_x4_t(r, vsb + (uint32_t)((ks * 16 + brow) * PA_STRIDE + p * 16 + bcol8) * 2);
            mma16816(cS[2 * p],     a, r[0], r[1]);
            mma16816(cS[2 * p + 1], a, r[2], r[3]);
        }
    }

    unsigned short* Sg = (unsigned short*)g_Sh + ((size_t)(bh * NCv + c)) * (HDv * HDv);
    int d0 = wm + (lane >> 2);
    int e0 = (lane & 3) * 2;
#pragma unroll
    for (int nb = 0; nb < 8; nb++) {
        *(uint32_t*)(Sg + d0 * 64 + nb * 8 + e0)       = pack_h2(cS[nb][0], cS[nb][1]);
        *(uint32_t*)(Sg + (d0 + 8) * 64 + nb * 8 + e0) = pack_h2(cS[nb][2], cS[nb][3]);
    }
}

// ---------------------------------------------------------------------------
// Phase B: register-resident exclusive prefix scan over fp16 S (fp32 run).
// ---------------------------------------------------------------------------
__global__ __launch_bounds__(256)
void phaseB_kernel()
{
    int bh  = blockIdx.x;
    int grp = blockIdx.y;
    int t   = threadIdx.x;
    int idx = grp * 256 + t;

    __half* Sg = g_Sh + (size_t)bh * NCv * (HDv * HDv) + idx;
    __half v[NCv];
#pragma unroll
    for (int c = 0; c < NCv; c++) v[c] = Sg[c * (HDv * HDv)];
    float run = 0.f;
#pragma unroll
    for (int c = 0; c < NCv; c++) {
        float x = __half2float(v[c]);
        Sg[c * (HDv * HDv)] = __float2half_rn(run);
        run += x;
    }

    if (grp == 0 && t < HDv) {
        float* zg = g_z + (size_t)bh * NCv * HDv + t;
        float zv[NCv];
#pragma unroll
        for (int c = 0; c < NCv; c++) zv[c] = zg[c * HDv];
        float rz = 0.f;
#pragma unroll
        for (int c = 0; c < NCv; c++) {
            float x = zv[c];
            zg[c * HDv] = rz;
            rz += x;
        }
    }
}

// ---------------------------------------------------------------------------
// Phase C (tensor): P = tril(QK^T); den = rowsum(P)+Q·z+eps;
// O = (P·V + Q·S_prev)/den, written fp16 into gA. S loaded fp16 directly.
// ---------------------------------------------------------------------------
#define QS_STRIDE 72
#define PHC_SMEM ((3 * 128 * QS_STRIDE + 64 * QS_STRIDE) * 2 + 64 * 4)

__global__ __launch_bounds__(256)
void phaseC_kernel()
{
    extern __shared__ __half smc[];
    __half* Qs = smc;
    __half* Ks = smc + 128 * QS_STRIDE;
    __half* Vs = smc + 2 * 128 * QS_STRIDE;
    __half* Sh = smc + 3 * 128 * QS_STRIDE;
    float*  zf = (float*)(smc + 3 * 128 * QS_STRIDE + 64 * QS_STRIDE);

    int blk = blockIdx.x;
    int c   = blk & (NCv - 1);
    int bh  = blk >> 5;
    int h   = bh & (Hv - 1);
    int b   = bh >> 4;
    int t   = threadIdx.x;
    int lane = t & 31, wid = t >> 5;

    size_t base = ((size_t)(b * Tv + c * Cv)) * Dv + h * HDv;

    for (int idx = t; idx < 128 * 8; idx += 256) {
        int row = idx >> 3, c8 = (idx & 7) << 3;
        size_t go = base + (size_t)row * Dv + c8;
        uint32_t so = (uint32_t)(row * QS_STRIDE + c8);
        *(uint4*)&Qs[so] = *(const uint4*)((const unsigned short*)g_Qh + go);
        *(uint4*)&Ks[so] = *(const uint4*)((const unsigned short*)g_Kh + go);
        *(uint4*)&Vs[so] = *(const uint4*)((const unsigned short*)g_Vh + go);
    }
    const unsigned short* Sg =
        (const unsigned short*)g_Sh + ((size_t)(bh * NCv + c)) * (HDv * HDv);
    for (int idx = t; idx < 512; idx += 256) {
        int row = idx >> 3, c8 = (idx & 7) << 3;
        *(uint4*)&Sh[row * QS_STRIDE + c8] = *(const uint4*)(Sg + row * 64 + c8);
    }
    if (t < 64) zf[t] = g_z[(size_t)(bh * NCv + c) * HDv + t];
    __syncthreads();

    uint32_t qsb = smem_u32(Qs), ksb = smem_u32(Ks), vsb = smem_u32(Vs), shb = smem_u32(Sh);

    int i0 = wid * 16;
    int arow = lane & 15, acol8 = (lane >> 4) << 3;

    uint32_t aQ[4][4];
#pragma unroll
    for (int ks = 0; ks < 4; ks++)
        ldsm_x4(aQ[ks], qsb + (uint32_t)((i0 + arow) * QS_STRIDE + ks * 16 + acol8) * 2);

    float cP[16][4];
#pragma unroll
    for (int nb = 0; nb < 16; nb++)
#pragma unroll
        for (int q = 0; q < 4; q++) cP[nb][q] = 0.f;

#pragma unroll
    for (int ks = 0; ks < 4; ks++) {
#pragma unroll
        for (int jb = 0; jb < 8; jb++) {
            uint32_t r[4];
            ldsm_x4(r, ksb + (uint32_t)((jb * 16 + arow) * QS_STRIDE + ks * 16 + acol8) * 2);
            mma16816(cP[2 * jb],     aQ[ks], r[0], r[2]);
            mma16816(cP[2 * jb + 1], aQ[ks], r[1], r[3]);
        }
    }

    int r0 = i0 + (lane >> 2);
    int cb = (lane & 3) * 2;
    float rs0 = 0.f, rs1 = 0.f;
#pragma unroll
    for (int nb = 0; nb < 16; nb++) {
        int j0 = nb * 8 + cb;
        if (j0     > r0)     cP[nb][0] = 0.f;
        if (j0 + 1 > r0)     cP[nb][1] = 0.f;
        if (j0     > r0 + 8) cP[nb][2] = 0.f;
        if (j0 + 1 > r0 + 8) cP[nb][3] = 0.f;
        rs0 += cP[nb][0] + cP[nb][1];
        rs1 += cP[nb][2] + cP[nb][3];
    }
    rs0 += __shfl_xor_sync(0xffffffffu, rs0, 1);
    rs0 += __shfl_xor_sync(0xffffffffu, rs0, 2);
    rs1 += __shfl_xor_sync(0xffffffffu, rs1, 1);
    rs1 += __shfl_xor_sync(0xffffffffu, rs1, 2);

    float qz0 = 0.f, qz1 = 0.f;
    for (int d = 0; d < 64; d++) {
        float zz = zf[d];
        qz0 += __half2float(Qs[r0 * QS_STRIDE + d]) * zz;
        qz1 += __half2float(Qs[(r0 + 8) * QS_STRIDE + d]) * zz;
    }
    float inv0 = 1.f / (rs0 + qz0 + 1e-6f);
    float inv1 = 1.f / (rs1 + qz1 + 1e-6f);

    uint32_t aP[8][4];
#pragma unroll
    for (int jk = 0; jk < 8; jk++) {
        aP[jk][0] = pack_h2(cP[2 * jk][0],     cP[2 * jk][1]);
        aP[jk][1] = pack_h2(cP[2 * jk][2],     cP[2 * jk][3]);
        aP[jk][2] = pack_h2(cP[2 * jk + 1][0], cP[2 * jk + 1][1]);
        aP[jk][3] = pack_h2(cP[2 * jk + 1][2], cP[2 * jk + 1][3]);
    }

    float cO[8][4];
#pragma unroll
    for (int nb = 0; nb < 8; nb++)
#pragma unroll
        for (int q = 0; q < 4; q++) cO[nb][q] = 0.f;

#pragma unroll
    for (int jk = 0; jk < 8; jk++) {
#pragma unroll
        for (int p = 0; p < 4; p++) {
            uint32_t r[4];
            ldsm_x4_t(r, vsb + (uint32_t)((jk * 16 + arow) * QS_STRIDE + p * 16 + acol8) * 2);
            mma16816(cO[2 * p],     aP[jk], r[0], r[1]);
            mma16816(cO[2 * p + 1], aP[jk], r[2], r[3]);
        }
    }
#pragma unroll
    for (int ks = 0; ks < 4; ks++) {
#pragma unroll
        for (int p = 0; p < 4; p++) {
            uint32_t r[4];
            ldsm_x4_t(r, shb + (uint32_t)((ks * 16 + arow) * QS_STRIDE + p * 16 + acol8) * 2);
            mma16816(cO[2 * p],     aQ[ks], r[0], r[1]);
            mma16816(cO[2 * p + 1], aQ[ks], r[2], r[3]);
        }
    }

    unsigned short* Yg = (unsigned short*)gA + base;
#pragma unroll
    for (int nb = 0; nb < 8; nb++) {
        int e = nb * 8 + cb;
        *(uint32_t*)(Yg + (size_t)r0 * Dv + e)       = pack_h2(cO[nb][0] * inv0, cO[nb][1] * inv0);
        *(uint32_t*)(Yg + (size_t)(r0 + 8) * Dv + e) = pack_h2(cO[nb][2] * inv1, cO[nb][3] * inv1);
    }
}

// ---------------------------------------------------------------------------
// Launch
// ---------------------------------------------------------------------------
extern "C" void kernel_launch(void* const* d_in, const int* in_sizes, int n_in,
                              void* d_out, int out_size)
{
    const float* x  = (const float*)d_in[0];
    const float* Wq = (const float*)d_in[1];
    const float* Wk = (const float*)d_in[2];
    const float* Wv = (const float*)d_in[3];
    const float* Wo = (const float*)d_in[4];
    float* out = (float*)d_out;

    cudaFuncSetAttribute(mma_gemm_kernel,
                         cudaFuncAttributeMaxDynamicSharedMemorySize, GEMM_SMEM);
    cudaFuncSetAttribute(phaseC_kernel,
                         cudaFuncAttributeMaxDynamicSharedMemorySize, PHC_SMEM);

    conv_kernel<<<CONV_BLOCKS, 256>>>(x, Wq, Wk, Wv, Wo);

    dim3 gqkv(1024 / 128, Mv / 128, 3);
    mma_gemm_kernel<<<gqkv, 256, GEMM_SMEM>>>(-1, nullptr, 0, 0);  // fp16 Q/K/V

    phaseA_kernel<<<Bv * Hv * NCv, 128>>>();
    dim3 gb(Bv * Hv, 16);
    phaseB_kernel<<<gb, 256>>>();
    phaseC_kernel<<<Bv * Hv * NCv, 256, PHC_SMEM>>>();             // fp16 Y into gA

    dim3 go(1024 / 128, Mv / 128);
    mma_gemm_kernel<<<go, 256, GEMM_SMEM>>>(3, out, 3, 0);         // out = Y@Wo
}

// round 15
// speedup vs baseline: 1.2072x; 1.0281x over previous
#include <cuda_runtime.h>
#include <cuda_fp16.h>
#include <math.h>
#include <stdint.h>

// Problem constants
#define Bv   4
#define Tv   4096
#define Dv   1024
#define Hv   16
#define HDv  64
#define Cv   128
#define NCv  32            // Tv / Cv
#define Mv   (Bv*Tv)       // 16384

// ---------------------------------------------------------------------------
// Scratch (device globals; no allocation allowed)
// ---------------------------------------------------------------------------
__device__ __align__(16) __half g_Sh[(size_t)Bv * Hv * NCv * HDv * HDv];  // fp16 S states
__device__ __align__(16) float g_z[(size_t)Bv * Hv * NCv * HDv];

__device__ __align__(16) __half gA[(size_t)Mv * Dv];   // x (QKV GEMMs), then Y (Wo GEMM)
__device__ __align__(16) __half gW[4 * 1024 * 1024];   // [wsel][K][N] fp16
__device__ __align__(16) __half g_Qh[(size_t)Mv * Dv];
__device__ __align__(16) __half g_Kh[(size_t)Mv * Dv];
__device__ __align__(16) __half g_Vh[(size_t)Mv * Dv];

// ---------------------------------------------------------------------------
// PTX helpers
// ---------------------------------------------------------------------------
__device__ __forceinline__ uint32_t smem_u32(const void* p) {
    uint32_t a;
    asm("{ .reg .u64 t; cvta.to.shared.u64 t, %1; cvt.u32.u64 %0, t; }" : "=r"(a) : "l"(p));
    return a;
}

__device__ __forceinline__ void cp_async16(uint32_t saddr, const void* g) {
    asm volatile("cp.async.cg.shared.global [%0], [%1], 16;" :: "r"(saddr), "l"(g) : "memory");
}

__device__ __forceinline__ void ldsm_x4(uint32_t* r, uint32_t addr) {
    asm volatile("ldmatrix.sync.aligned.m8n8.x4.shared.b16 {%0,%1,%2,%3}, [%4];"
                 : "=r"(r[0]), "=r"(r[1]), "=r"(r[2]), "=r"(r[3]) : "r"(addr));
}
__device__ __forceinline__ void ldsm_x4_t(uint32_t* r, uint32_t addr) {
    asm volatile("ldmatrix.sync.aligned.m8n8.x4.trans.shared.b16 {%0,%1,%2,%3}, [%4];"
                 : "=r"(r[0]), "=r"(r[1]), "=r"(r[2]), "=r"(r[3]) : "r"(addr));
}

__device__ __forceinline__ void mma16816(float* c, const uint32_t* a, uint32_t b0, uint32_t b1) {
    asm volatile(
        "mma.sync.aligned.m16n8k16.row.col.f32.f16.f16.f32 "
        "{%0,%1,%2,%3}, {%4,%5,%6,%7}, {%8,%9}, {%0,%1,%2,%3};"
        : "+f"(c[0]), "+f"(c[1]), "+f"(c[2]), "+f"(c[3])
        : "r"(a[0]), "r"(a[1]), "r"(a[2]), "r"(a[3]), "r"(b0), "r"(b1));
}

__device__ __forceinline__ uint32_t pack_h2(float lo, float hi) {
    __half2 h = __floats2half2_rn(lo, hi);
    return *(uint32_t*)&h;
}

// ---------------------------------------------------------------------------
// Fused fp32 -> fp16 conversion, MLP=4 (4 independent float4 per thread).
// Blocks [0, 4096): x -> gA. Blocks [4096, 5120): W -> gW.
// ---------------------------------------------------------------------------
#define CONV_A_BLOCKS 4096
#define CONV_W_BLOCKS 1024
#define CONV_BLOCKS   (CONV_A_BLOCKS + CONV_W_BLOCKS)

__global__ __launch_bounds__(256)
void conv_kernel(const float* __restrict__ x,
                 const float* __restrict__ W0, const float* __restrict__ W1,
                 const float* __restrict__ W2, const float* __restrict__ W3)
{
    int blk = blockIdx.x;
    int t   = threadIdx.x;
    const float* src;
    unsigned short* dst;
    size_t base_f4;
    if (blk < CONV_A_BLOCKS) {
        src = x;
        dst = (unsigned short*)gA;
        base_f4 = (size_t)blk * 1024;
    } else {
        int wb = blk - CONV_A_BLOCKS;
        int wsel = wb >> 8;
        src = (wsel == 0) ? W0 : (wsel == 1) ? W1 : (wsel == 2) ? W2 : W3;
        dst = (unsigned short*)(gW + ((size_t)wsel << 20));
        base_f4 = (size_t)(wb & 255) * 1024;
    }

    float4 v[4];
#pragma unroll
    for (int k = 0; k < 4; k++)
        v[k] = *(const float4*)(src + (base_f4 + t + (size_t)k * 256) * 4);
#pragma unroll
    for (int k = 0; k < 4; k++) {
        ushort4 h;
        h.x = __half_as_ushort(__float2half_rn(v[k].x));
        h.y = __half_as_ushort(__float2half_rn(v[k].y));
        h.z = __half_as_ushort(__float2half_rn(v[k].z));
        h.w = __half_as_ushort(__float2half_rn(v[k].w));
        *(ushort4*)(dst + (base_f4 + t + (size_t)k * 256) * 4) = h;
    }
}

// ---------------------------------------------------------------------------
// fp16 HMMA GEMM: C = A[M,K] @ W[K,N]. CTA 128x128, BK=32, 4-stage cp.async,
// 4 warps (64x64 warp tiles), 3 CTAs/SM. Measured saddle point between the
// tensor-issue, smem-crossbar and regfile constraints of legacy mma.sync.
// ---------------------------------------------------------------------------
#define ASTRIDE 40
#define BSTRIDE 136
#define A_SM    (128 * ASTRIDE * 2)      // 10240
#define B_SM    (32 * BSTRIDE * 2)       // 8704
#define STAGE_BYTES (A_SM + B_SM)        // 18944
#define GEMM_SMEM (4 * STAGE_BYTES)      // 75776

__device__ __forceinline__ void gemm_load_stage(
    uint32_t sb, int t, int m0, int n0, int kt,
    const __half* pA, const __half* pB)
{
    int k0 = kt * 32;
#pragma unroll
    for (int it = 0; it < 4; it++) {
        int idx = t + it * 128;
        int row = idx >> 2, c8 = (idx & 3) << 3;
        cp_async16(sb + (uint32_t)(row * ASTRIDE + c8) * 2,
                   pA + (size_t)(m0 + row) * 1024 + k0 + c8);
    }
#pragma unroll
    for (int it = 0; it < 4; it++) {
        int idx = t + it * 128;
        int row = idx >> 4, c8 = (idx & 15) << 3;
        cp_async16(sb + A_SM + (uint32_t)(row * BSTRIDE + c8) * 2,
                   pB + (size_t)(k0 + row) * 1024 + n0 + c8);
    }
    asm volatile("cp.async.commit_group;" ::: "memory");
}

__global__ __launch_bounds__(128, 3)
void mma_gemm_kernel(int wsel, float* __restrict__ Cext, int csel, int fmap)
{
    extern __shared__ __half smh[];
    if (wsel < 0) { wsel = blockIdx.z; csel = blockIdx.z; fmap = (blockIdx.z < 2); }

    const __half* pA = gA;
    const __half* pB = gW + (size_t)wsel * 1024 * 1024;

    int t = threadIdx.x, lane = t & 31, wid = t >> 5;
    int n0 = blockIdx.x * 128;
    int m0 = blockIdx.y * 128;
    uint32_t sbase = smem_u32(smh);

    int wm = (wid >> 1) * 64;
    int wn = (wid & 1) * 64;

    float acc[4][8][4];
#pragma unroll
    for (int mi = 0; mi < 4; mi++)
#pragma unroll
        for (int nt = 0; nt < 8; nt++)
#pragma unroll
            for (int q = 0; q < 4; q++) acc[mi][nt][q] = 0.f;

    gemm_load_stage(sbase, t, m0, n0, 0, pA, pB);
    gemm_load_stage(sbase + STAGE_BYTES, t, m0, n0, 1, pA, pB);
    gemm_load_stage(sbase + 2 * STAGE_BYTES, t, m0, n0, 2, pA, pB);

    for (int kt = 0; kt < 32; kt++) {
        if (kt <= 29)      asm volatile("cp.async.wait_group 2;" ::: "memory");
        else if (kt == 30) asm volatile("cp.async.wait_group 1;" ::: "memory");
        else               asm volatile("cp.async.wait_group 0;" ::: "memory");
        __syncthreads();
        if (kt + 3 < 32)
            gemm_load_stage(sbase + (uint32_t)((kt + 3) & 3) * STAGE_BYTES,
                            t, m0, n0, kt + 3, pA, pB);

        uint32_t sb = sbase + (uint32_t)(kt & 3) * STAGE_BYTES;
#pragma unroll
        for (int ks = 0; ks < 2; ks++) {
            uint32_t aF[4][4], bF[16];
            int arow = lane & 15;
            int acol = ks * 16 + ((lane >> 4) << 3);
#pragma unroll
            for (int mi = 0; mi < 4; mi++)
                ldsm_x4(aF[mi], sb + (uint32_t)((wm + mi * 16 + arow) * ASTRIDE + acol) * 2);

            int brow = ks * 16 + (lane & 15);
#pragma unroll
            for (int p = 0; p < 4; p++) {
                int bcol = wn + p * 16 + ((lane >> 4) << 3);
                ldsm_x4_t(&bF[p * 4], sb + A_SM + (uint32_t)(brow * BSTRIDE + bcol) * 2);
            }
#pragma unroll
            for (int mi = 0; mi < 4; mi++)
#pragma unroll
                for (int nt = 0; nt < 8; nt++)
                    mma16816(acc[mi][nt], aF[mi],
                             bF[(nt >> 1) * 4 + (nt & 1) * 2], bF[(nt >> 1) * 4 + (nt & 1) * 2 + 1]);
        }
    }

    int rbase = m0 + wm + (lane >> 2);
    int cb0 = wn + (lane & 3) * 2;
#pragma unroll
    for (int mi = 0; mi < 4; mi++) {
        int row = rbase + mi * 16;
#pragma unroll
        for (int nt = 0; nt < 8; nt++) {
            float v0 = acc[mi][nt][0], v1 = acc[mi][nt][1];
            float v2 = acc[mi][nt][2], v3 = acc[mi][nt][3];
            if (fmap) {
                v0 = v0 > 0.f ? v0 + 1.f : expf(v0);
                v1 = v1 > 0.f ? v1 + 1.f : expf(v1);
                v2 = v2 > 0.f ? v2 + 1.f : expf(v2);
                v3 = v3 > 0.f ? v3 + 1.f : expf(v3);
            }
            if (csel < 3) {
                __half* Ch = (csel == 0) ? g_Qh : (csel == 1) ? g_Kh : g_Vh;
                *(uint32_t*)((unsigned short*)Ch + (size_t)row * 1024 + n0 + cb0 + nt * 8)
                    = pack_h2(v0, v1);
                *(uint32_t*)((unsigned short*)Ch + (size_t)(row + 8) * 1024 + n0 + cb0 + nt * 8)
                    = pack_h2(v2, v3);
            } else {
                float2 o0; o0.x = v0; o0.y = v1;
                float2 o1; o1.x = v2; o1.y = v3;
                *(float2*)(Cext + (size_t)row * 1024 + n0 + cb0 + nt * 8) = o0;
                *(float2*)(Cext + (size_t)(row + 8) * 1024 + n0 + cb0 + nt * 8) = o1;
            }
        }
    }
}

// ---------------------------------------------------------------------------
// Phase A (tensor): S_c = K_c^T V_c (fp16 out), z_c = col sums of K (fp32).
// K^T A-fragments built directly with ldmatrix.trans (no smem transpose).
// ---------------------------------------------------------------------------
#define PA_STRIDE 72

__global__ __launch_bounds__(128)
void phaseA_kernel()
{
    __shared__ __half Ks[128 * PA_STRIDE];
    __shared__ __half Vs[128 * PA_STRIDE];

    int blk = blockIdx.x;
    int c   = blk & (NCv - 1);
    int bh  = blk >> 5;
    int h   = bh & (Hv - 1);
    int b   = bh >> 4;
    int t   = threadIdx.x;
    int lane = t & 31, wid = t >> 5;

    size_t base = ((size_t)(b * Tv + c * Cv)) * Dv + h * HDv;

    for (int idx = t; idx < 128 * 8; idx += 128) {
        int row = idx >> 3, c8 = (idx & 7) << 3;
        size_t go = base + (size_t)row * Dv + c8;
        *(uint4*)&Ks[row * PA_STRIDE + c8] = *(const uint4*)((const unsigned short*)g_Kh + go);
        *(uint4*)&Vs[row * PA_STRIDE + c8] = *(const uint4*)((const unsigned short*)g_Vh + go);
    }
    __syncthreads();

    if (t < 64) {
        float s = 0.f;
        for (int tt = 0; tt < 128; tt++) s += __half2float(Ks[tt * PA_STRIDE + t]);
        g_z[(size_t)(bh * NCv + c) * HDv + t] = s;
    }

    uint32_t ksb = smem_u32(Ks);
    uint32_t vsb = smem_u32(Vs);

    int wm = wid * 16;
    float cS[8][4];
#pragma unroll
    for (int nb = 0; nb < 8; nb++)
#pragma unroll
        for (int q = 0; q < 4; q++) cS[nb][q] = 0.f;

    int a_rofs = ((lane >> 4) << 3) + (lane & 7);
    int a_cofs = wm + (((lane >> 3) & 1) << 3);
    int brow = lane & 15, bcol8 = (lane >> 4) << 3;

#pragma unroll
    for (int ks = 0; ks < 8; ks++) {
        uint32_t a[4];
        ldsm_x4_t(a, ksb + (uint32_t)((ks * 16 + a_rofs) * PA_STRIDE + a_cofs) * 2);
#pragma unroll
        for (int p = 0; p < 4; p++) {
            uint32_t r[4];
            ldsm_x4_t(r, vsb + (uint32_t)((ks * 16 + brow) * PA_STRIDE + p * 16 + bcol8) * 2);
            mma16816(cS[2 * p],     a, r[0], r[1]);
            mma16816(cS[2 * p + 1], a, r[2], r[3]);
        }
    }

    unsigned short* Sg = (unsigned short*)g_Sh + ((size_t)(bh * NCv + c)) * (HDv * HDv);
    int d0 = wm + (lane >> 2);
    int e0 = (lane & 3) * 2;
#pragma unroll
    for (int nb = 0; nb < 8; nb++) {
        *(uint32_t*)(Sg + d0 * 64 + nb * 8 + e0)       = pack_h2(cS[nb][0], cS[nb][1]);
        *(uint32_t*)(Sg + (d0 + 8) * 64 + nb * 8 + e0) = pack_h2(cS[nb][2], cS[nb][3]);
    }
}

// ---------------------------------------------------------------------------
// Phase B: register-resident exclusive prefix scan over fp16 S (fp32 run),
// MLP=32: all strided loads issued before the serial add chain.
// ---------------------------------------------------------------------------
__global__ __launch_bounds__(256)
void phaseB_kernel()
{
    int bh  = blockIdx.x;
    int grp = blockIdx.y;
    int t   = threadIdx.x;
    int idx = grp * 256 + t;

    __half* Sg = g_Sh + (size_t)bh * NCv * (HDv * HDv) + idx;
    __half v[NCv];
#pragma unroll
    for (int c = 0; c < NCv; c++) v[c] = Sg[c * (HDv * HDv)];
    float run = 0.f;
#pragma unroll
    for (int c = 0; c < NCv; c++) {
        float x = __half2float(v[c]);
        Sg[c * (HDv * HDv)] = __float2half_rn(run);
        run += x;
    }

    if (grp == 0 && t < HDv) {
        float* zg = g_z + (size_t)bh * NCv * HDv + t;
        float zv[NCv];
#pragma unroll
        for (int c = 0; c < NCv; c++) zv[c] = zg[c * HDv];
        float rz = 0.f;
#pragma unroll
        for (int c = 0; c < NCv; c++) {
            float x = zv[c];
            zg[c * HDv] = rz;
            rz += x;
        }
    }
}

// ---------------------------------------------------------------------------
// Phase C (tensor): P = tril(QK^T); den = rowsum(P)+Q·z+eps;
// O = (P·V + Q·S_prev)/den, written fp16 into gA. S loaded fp16 directly.
// ---------------------------------------------------------------------------
#define QS_STRIDE 72
#define PHC_SMEM ((3 * 128 * QS_STRIDE + 64 * QS_STRIDE) * 2 + 64 * 4)

__global__ __launch_bounds__(256)
void phaseC_kernel()
{
    extern __shared__ __half smc[];
    __half* Qs = smc;
    __half* Ks = smc + 128 * QS_STRIDE;
    __half* Vs = smc + 2 * 128 * QS_STRIDE;
    __half* Sh = smc + 3 * 128 * QS_STRIDE;
    float*  zf = (float*)(smc + 3 * 128 * QS_STRIDE + 64 * QS_STRIDE);

    int blk = blockIdx.x;
    int c   = blk & (NCv - 1);
    int bh  = blk >> 5;
    int h   = bh & (Hv - 1);
    int b   = bh >> 4;
    int t   = threadIdx.x;
    int lane = t & 31, wid = t >> 5;

    size_t base = ((size_t)(b * Tv + c * Cv)) * Dv + h * HDv;

    for (int idx = t; idx < 128 * 8; idx += 256) {
        int row = idx >> 3, c8 = (idx & 7) << 3;
        size_t go = base + (size_t)row * Dv + c8;
        uint32_t so = (uint32_t)(row * QS_STRIDE + c8);
        *(uint4*)&Qs[so] = *(const uint4*)((const unsigned short*)g_Qh + go);
        *(uint4*)&Ks[so] = *(const uint4*)((const unsigned short*)g_Kh + go);
        *(uint4*)&Vs[so] = *(const uint4*)((const unsigned short*)g_Vh + go);
    }
    const unsigned short* Sg =
        (const unsigned short*)g_Sh + ((size_t)(bh * NCv + c)) * (HDv * HDv);
    for (int idx = t; idx < 512; idx += 256) {
        int row = idx >> 3, c8 = (idx & 7) << 3;
        *(uint4*)&Sh[row * QS_STRIDE + c8] = *(const uint4*)(Sg + row * 64 + c8);
    }
    if (t < 64) zf[t] = g_z[(size_t)(bh * NCv + c) * HDv + t];
    __syncthreads();

    uint32_t qsb = smem_u32(Qs), ksb = smem_u32(Ks), vsb = smem_u32(Vs), shb = smem_u32(Sh);

    int i0 = wid * 16;
    int arow = lane & 15, acol8 = (lane >> 4) << 3;

    uint32_t aQ[4][4];
#pragma unroll
    for (int ks = 0; ks < 4; ks++)
        ldsm_x4(aQ[ks], qsb + (uint32_t)((i0 + arow) * QS_STRIDE + ks * 16 + acol8) * 2);

    float cP[16][4];
#pragma unroll
    for (int nb = 0; nb < 16; nb++)
#pragma unroll
        for (int q = 0; q < 4; q++) cP[nb][q] = 0.f;

#pragma unroll
    for (int ks = 0; ks < 4; ks++) {
#pragma unroll
        for (int jb = 0; jb < 8; jb++) {
            uint32_t r[4];
            ldsm_x4(r, ksb + (uint32_t)((jb * 16 + arow) * QS_STRIDE + ks * 16 + acol8) * 2);
            mma16816(cP[2 * jb],     aQ[ks], r[0], r[2]);
            mma16816(cP[2 * jb + 1], aQ[ks], r[1], r[3]);
        }
    }

    int r0 = i0 + (lane >> 2);
    int cb = (lane & 3) * 2;
    float rs0 = 0.f, rs1 = 0.f;
#pragma unroll
    for (int nb = 0; nb < 16; nb++) {
        int j0 = nb * 8 + cb;
        if (j0     > r0)     cP[nb][0] = 0.f;
        if (j0 + 1 > r0)     cP[nb][1] = 0.f;
        if (j0     > r0 + 8) cP[nb][2] = 0.f;
        if (j0 + 1 > r0 + 8) cP[nb][3] = 0.f;
        rs0 += cP[nb][0] + cP[nb][1];
        rs1 += cP[nb][2] + cP[nb][3];
    }
    rs0 += __shfl_xor_sync(0xffffffffu, rs0, 1);
    rs0 += __shfl_xor_sync(0xffffffffu, rs0, 2);
    rs1 += __shfl_xor_sync(0xffffffffu, rs1, 1);
    rs1 += __shfl_xor_sync(0xffffffffu, rs1, 2);

    float qz0 = 0.f, qz1 = 0.f;
    for (int d = 0; d < 64; d++) {
        float zz = zf[d];
        qz0 += __half2float(Qs[r0 * QS_STRIDE + d]) * zz;
        qz1 += __half2float(Qs[(r0 + 8) * QS_STRIDE + d]) * zz;
    }
    float inv0 = 1.f / (rs0 + qz0 + 1e-6f);
    float inv1 = 1.f / (rs1 + qz1 + 1e-6f);

    uint32_t aP[8][4];
#pragma unroll
    for (int jk = 0; jk < 8; jk++) {
        aP[jk][0] = pack_h2(cP[2 * jk][0],     cP[2 * jk][1]);
        aP[jk][1] = pack_h2(cP[2 * jk][2],     cP[2 * jk][3]);
        aP[jk][2] = pack_h2(cP[2 * jk + 1][0], cP[2 * jk + 1][1]);
        aP[jk][3] = pack_h2(cP[2 * jk + 1][2], cP[2 * jk + 1][3]);
    }

    float cO[8][4];
#pragma unroll
    for (int nb = 0; nb < 8; nb++)
#pragma unroll
        for (int q = 0; q < 4; q++) cO[nb][q] = 0.f;

#pragma unroll
    for (int jk = 0; jk < 8; jk++) {
#pragma unroll
        for (int p = 0; p < 4; p++) {
            uint32_t r[4];
            ldsm_x4_t(r, vsb + (uint32_t)((jk * 16 + arow) * QS_STRIDE + p * 16 + acol8) * 2);
            mma16816(cO[2 * p],     aP[jk], r[0], r[1]);
            mma16816(cO[2 * p + 1], aP[jk], r[2], r[3]);
        }
    }
#pragma unroll
    for (int ks = 0; ks < 4; ks++) {
#pragma unroll
        for (int p = 0; p < 4; p++) {
            uint32_t r[4];
            ldsm_x4_t(r, shb + (uint32_t)((ks * 16 + arow) * QS_STRIDE + p * 16 + acol8) * 2);
            mma16816(cO[2 * p],     aQ[ks], r[0], r[1]);
            mma16816(cO[2 * p + 1], aQ[ks], r[2], r[3]);
        }
    }

    unsigned short* Yg = (unsigned short*)gA + base;
#pragma unroll
    for (int nb = 0; nb < 8; nb++) {
        int e = nb * 8 + cb;
        *(uint32_t*)(Yg + (size_t)r0 * Dv + e)       = pack_h2(cO[nb][0] * inv0, cO[nb][1] * inv0);
        *(uint32_t*)(Yg + (size_t)(r0 + 8) * Dv + e) = pack_h2(cO[nb][2] * inv1, cO[nb][3] * inv1);
    }
}

// ---------------------------------------------------------------------------
// Launch
// ---------------------------------------------------------------------------
extern "C" void kernel_launch(void* const* d_in, const int* in_sizes, int n_in,
                              void* d_out, int out_size)
{
    const float* x  = (const float*)d_in[0];
    const float* Wq = (const float*)d_in[1];
    const float* Wk = (const float*)d_in[2];
    const float* Wv = (const float*)d_in[3];
    const float* Wo = (const float*)d_in[4];
    float* out = (float*)d_out;

    cudaFuncSetAttribute(mma_gemm_kernel,
                         cudaFuncAttributeMaxDynamicSharedMemorySize, GEMM_SMEM);
    cudaFuncSetAttribute(phaseC_kernel,
                         cudaFuncAttributeMaxDynamicSharedMemorySize, PHC_SMEM);

    conv_kernel<<<CONV_BLOCKS, 256>>>(x, Wq, Wk, Wv, Wo);

    dim3 gqkv(1024 / 128, Mv / 128, 3);
    mma_gemm_kernel<<<gqkv, 128, GEMM_SMEM>>>(-1, nullptr, 0, 0);  // fp16 Q/K/V

    phaseA_kernel<<<Bv * Hv * NCv, 128>>>();
    dim3 gb(Bv * Hv, 16);
    phaseB_kernel<<<gb, 256>>>();
    phaseC_kernel<<<Bv * Hv * NCv, 256, PHC_SMEM>>>();             // fp16 Y into gA

    dim3 go(1024 / 128, Mv / 128);
    mma_gemm_kernel<<<go, 128, GEMM_SMEM>>>(3, out, 3, 0);         // out = Y@Wo
}

// round 16
// speedup vs baseline: 1.2074x; 1.0002x over previous
#include <cuda_runtime.h>
#include <cuda_fp16.h>
#include <math.h>
#include <stdint.h>

// Problem constants
#define Bv   4
#define Tv   4096
#define Dv   1024
#define Hv   16
#define HDv  64
#define Cv   128
#define NCv  32            // Tv / Cv
#define Mv   (Bv*Tv)       // 16384

// ---------------------------------------------------------------------------
// Scratch (device globals; no allocation allowed)
// ---------------------------------------------------------------------------
__device__ __align__(16) __half g_Sh[(size_t)Bv * Hv * NCv * HDv * HDv];  // fp16 S states
__device__ __align__(16) float g_z[(size_t)Bv * Hv * NCv * HDv];

__device__ __align__(16) __half gA[(size_t)Mv * Dv];   // x (QKV GEMMs), then Y (Wo GEMM)
__device__ __align__(16) __half gW[4 * 1024 * 1024];   // [wsel][K][N] fp16
__device__ __align__(16) __half g_Qh[(size_t)Mv * Dv];
__device__ __align__(16) __half g_Kh[(size_t)Mv * Dv];
__device__ __align__(16) __half g_Vh[(size_t)Mv * Dv];

// ---------------------------------------------------------------------------
// PTX helpers
// ---------------------------------------------------------------------------
__device__ __forceinline__ uint32_t smem_u32(const void* p) {
    uint32_t a;
    asm("{ .reg .u64 t; cvta.to.shared.u64 t, %1; cvt.u32.u64 %0, t; }" : "=r"(a) : "l"(p));
    return a;
}

__device__ __forceinline__ void cp_async16(uint32_t saddr, const void* g) {
    asm volatile("cp.async.cg.shared.global [%0], [%1], 16;" :: "r"(saddr), "l"(g) : "memory");
}

__device__ __forceinline__ void ldsm_x4(uint32_t* r, uint32_t addr) {
    asm volatile("ldmatrix.sync.aligned.m8n8.x4.shared.b16 {%0,%1,%2,%3}, [%4];"
                 : "=r"(r[0]), "=r"(r[1]), "=r"(r[2]), "=r"(r[3]) : "r"(addr));
}
__device__ __forceinline__ void ldsm_x4_t(uint32_t* r, uint32_t addr) {
    asm volatile("ldmatrix.sync.aligned.m8n8.x4.trans.shared.b16 {%0,%1,%2,%3}, [%4];"
                 : "=r"(r[0]), "=r"(r[1]), "=r"(r[2]), "=r"(r[3]) : "r"(addr));
}

__device__ __forceinline__ void mma16816(float* c, const uint32_t* a, uint32_t b0, uint32_t b1) {
    asm volatile(
        "mma.sync.aligned.m16n8k16.row.col.f32.f16.f16.f32 "
        "{%0,%1,%2,%3}, {%4,%5,%6,%7}, {%8,%9}, {%0,%1,%2,%3};"
        : "+f"(c[0]), "+f"(c[1]), "+f"(c[2]), "+f"(c[3])
        : "r"(a[0]), "r"(a[1]), "r"(a[2]), "r"(a[3]), "r"(b0), "r"(b1));
}

__device__ __forceinline__ uint32_t pack_h2(float lo, float hi) {
    __half2 h = __floats2half2_rn(lo, hi);
    return *(uint32_t*)&h;
}

// ---------------------------------------------------------------------------
// Fused fp32 -> fp16 conversion, MLP=4 (4 independent float4 per thread).
// Blocks [0, 4096): x -> gA. Blocks [4096, 5120): W -> gW.
// ---------------------------------------------------------------------------
#define CONV_A_BLOCKS 4096
#define CONV_W_BLOCKS 1024
#define CONV_BLOCKS   (CONV_A_BLOCKS + CONV_W_BLOCKS)

__global__ __launch_bounds__(256)
void conv_kernel(const float* __restrict__ x,
                 const float* __restrict__ W0, const float* __restrict__ W1,
                 const float* __restrict__ W2, const float* __restrict__ W3)
{
    int blk = blockIdx.x;
    int t   = threadIdx.x;
    const float* src;
    unsigned short* dst;
    size_t base_f4;
    if (blk < CONV_A_BLOCKS) {
        src = x;
        dst = (unsigned short*)gA;
        base_f4 = (size_t)blk * 1024;
    } else {
        int wb = blk - CONV_A_BLOCKS;
        int wsel = wb >> 8;
        src = (wsel == 0) ? W0 : (wsel == 1) ? W1 : (wsel == 2) ? W2 : W3;
        dst = (unsigned short*)(gW + ((size_t)wsel << 20));
        base_f4 = (size_t)(wb & 255) * 1024;
    }

    float4 v[4];
#pragma unroll
    for (int k = 0; k < 4; k++)
        v[k] = *(const float4*)(src + (base_f4 + t + (size_t)k * 256) * 4);
#pragma unroll
    for (int k = 0; k < 4; k++) {
        ushort4 h;
        h.x = __half_as_ushort(__float2half_rn(v[k].x));
        h.y = __half_as_ushort(__float2half_rn(v[k].y));
        h.z = __half_as_ushort(__float2half_rn(v[k].z));
        h.w = __half_as_ushort(__float2half_rn(v[k].w));
        *(ushort4*)(dst + (base_f4 + t + (size_t)k * 256) * 4) = h;
    }
}

// ---------------------------------------------------------------------------
// fp16 HMMA GEMM: C = A[M,K] @ W[K,N]. CTA 128x128, BK=32, 4-stage cp.async,
// 4 warps (64x64 warp tiles), 3 CTAs/SM. Measured saddle point between the
// tensor-issue, smem-crossbar and regfile constraints of legacy mma.sync.
// ---------------------------------------------------------------------------
#define ASTRIDE 40
#define BSTRIDE 136
#define A_SM    (128 * ASTRIDE * 2)      // 10240
#define B_SM    (32 * BSTRIDE * 2)       // 8704
#define STAGE_BYTES (A_SM + B_SM)        // 18944
#define GEMM_SMEM (4 * STAGE_BYTES)      // 75776

__device__ __forceinline__ void gemm_load_stage(
    uint32_t sb, int t, int m0, int n0, int kt,
    const __half* pA, const __half* pB)
{
    int k0 = kt * 32;
#pragma unroll
    for (int it = 0; it < 4; it++) {
        int idx = t + it * 128;
        int row = idx >> 2, c8 = (idx & 3) << 3;
        cp_async16(sb + (uint32_t)(row * ASTRIDE + c8) * 2,
                   pA + (size_t)(m0 + row) * 1024 + k0 + c8);
    }
#pragma unroll
    for (int it = 0; it < 4; it++) {
        int idx = t + it * 128;
        int row = idx >> 4, c8 = (idx & 15) << 3;
        cp_async16(sb + A_SM + (uint32_t)(row * BSTRIDE + c8) * 2,
                   pB + (size_t)(k0 + row) * 1024 + n0 + c8);
    }
    asm volatile("cp.async.commit_group;" ::: "memory");
}

__global__ __launch_bounds__(128, 3)
void mma_gemm_kernel(int wsel, float* __restrict__ Cext, int csel, int fmap)
{
    extern __shared__ __half smh[];
    if (wsel < 0) { wsel = blockIdx.z; csel = blockIdx.z; fmap = (blockIdx.z < 2); }

    const __half* pA = gA;
    const __half* pB = gW + (size_t)wsel * 1024 * 1024;

    int t = threadIdx.x, lane = t & 31, wid = t >> 5;
    int n0 = blockIdx.x * 128;
    int m0 = blockIdx.y * 128;
    uint32_t sbase = smem_u32(smh);

    int wm = (wid >> 1) * 64;
    int wn = (wid & 1) * 64;

    float acc[4][8][4];
#pragma unroll
    for (int mi = 0; mi < 4; mi++)
#pragma unroll
        for (int nt = 0; nt < 8; nt++)
#pragma unroll
            for (int q = 0; q < 4; q++) acc[mi][nt][q] = 0.f;

    gemm_load_stage(sbase, t, m0, n0, 0, pA, pB);
    gemm_load_stage(sbase + STAGE_BYTES, t, m0, n0, 1, pA, pB);
    gemm_load_stage(sbase + 2 * STAGE_BYTES, t, m0, n0, 2, pA, pB);

    for (int kt = 0; kt < 32; kt++) {
        if (kt <= 29)      asm volatile("cp.async.wait_group 2;" ::: "memory");
        else if (kt == 30) asm volatile("cp.async.wait_group 1;" ::: "memory");
        else               asm volatile("cp.async.wait_group 0;" ::: "memory");
        __syncthreads();
        if (kt + 3 < 32)
            gemm_load_stage(sbase + (uint32_t)((kt + 3) & 3) * STAGE_BYTES,
                            t, m0, n0, kt + 3, pA, pB);

        uint32_t sb = sbase + (uint32_t)(kt & 3) * STAGE_BYTES;
#pragma unroll
        for (int ks = 0; ks < 2; ks++) {
            uint32_t aF[4][4], bF[16];
            int arow = lane & 15;
            int acol = ks * 16 + ((lane >> 4) << 3);
#pragma unroll
            for (int mi = 0; mi < 4; mi++)
                ldsm_x4(aF[mi], sb + (uint32_t)((wm + mi * 16 + arow) * ASTRIDE + acol) * 2);

            int brow = ks * 16 + (lane & 15);
#pragma unroll
            for (int p = 0; p < 4; p++) {
                int bcol = wn + p * 16 + ((lane >> 4) << 3);
                ldsm_x4_t(&bF[p * 4], sb + A_SM + (uint32_t)(brow * BSTRIDE + bcol) * 2);
            }
#pragma unroll
            for (int mi = 0; mi < 4; mi++)
#pragma unroll
                for (int nt = 0; nt < 8; nt++)
                    mma16816(acc[mi][nt], aF[mi],
                             bF[(nt >> 1) * 4 + (nt & 1) * 2], bF[(nt >> 1) * 4 + (nt & 1) * 2 + 1]);
        }
    }

    int rbase = m0 + wm + (lane >> 2);
    int cb0 = wn + (lane & 3) * 2;
#pragma unroll
    for (int mi = 0; mi < 4; mi++) {
        int row = rbase + mi * 16;
#pragma unroll
        for (int nt = 0; nt < 8; nt++) {
            float v0 = acc[mi][nt][0], v1 = acc[mi][nt][1];
            float v2 = acc[mi][nt][2], v3 = acc[mi][nt][3];
            if (fmap) {
                v0 = v0 > 0.f ? v0 + 1.f : expf(v0);
                v1 = v1 > 0.f ? v1 + 1.f : expf(v1);
                v2 = v2 > 0.f ? v2 + 1.f : expf(v2);
                v3 = v3 > 0.f ? v3 + 1.f : expf(v3);
            }
            if (csel < 3) {
                __half* Ch = (csel == 0) ? g_Qh : (csel == 1) ? g_Kh : g_Vh;
                *(uint32_t*)((unsigned short*)Ch + (size_t)row * 1024 + n0 + cb0 + nt * 8)
                    = pack_h2(v0, v1);
                *(uint32_t*)((unsigned short*)Ch + (size_t)(row + 8) * 1024 + n0 + cb0 + nt * 8)
                    = pack_h2(v2, v3);
            } else {
                float2 o0; o0.x = v0; o0.y = v1;
                float2 o1; o1.x = v2; o1.y = v3;
                *(float2*)(Cext + (size_t)row * 1024 + n0 + cb0 + nt * 8) = o0;
                *(float2*)(Cext + (size_t)(row + 8) * 1024 + n0 + cb0 + nt * 8) = o1;
            }
        }
    }
}

// ---------------------------------------------------------------------------
// Phase A (tensor): S_c = K_c^T V_c (fp16 out), z_c = col sums of K (fp32).
// K^T A-fragments built directly with ldmatrix.trans (no smem transpose).
// ---------------------------------------------------------------------------
#define PA_STRIDE 72

__global__ __launch_bounds__(128)
void phaseA_kernel()
{
    __shared__ __half Ks[128 * PA_STRIDE];
    __shared__ __half Vs[128 * PA_STRIDE];

    int blk = blockIdx.x;
    int c   = blk & (NCv - 1);
    int bh  = blk >> 5;
    int h   = bh & (Hv - 1);
    int b   = bh >> 4;
    int t   = threadIdx.x;
    int lane = t & 31, wid = t >> 5;

    size_t base = ((size_t)(b * Tv + c * Cv)) * Dv + h * HDv;

    for (int idx = t; idx < 128 * 8; idx += 128) {
        int row = idx >> 3, c8 = (idx & 7) << 3;
        size_t go = base + (size_t)row * Dv + c8;
        *(uint4*)&Ks[row * PA_STRIDE + c8] = *(const uint4*)((const unsigned short*)g_Kh + go);
        *(uint4*)&Vs[row * PA_STRIDE + c8] = *(const uint4*)((const unsigned short*)g_Vh + go);
    }
    __syncthreads();

    if (t < 64) {
        float s = 0.f;
        for (int tt = 0; tt < 128; tt++) s += __half2float(Ks[tt * PA_STRIDE + t]);
        g_z[(size_t)(bh * NCv + c) * HDv + t] = s;
    }

    uint32_t ksb = smem_u32(Ks);
    uint32_t vsb = smem_u32(Vs);

    int wm = wid * 16;
    float cS[8][4];
#pragma unroll
    for (int nb = 0; nb < 8; nb++)
#pragma unroll
        for (int q = 0; q < 4; q++) cS[nb][q] = 0.f;

    int a_rofs = ((lane >> 4) << 3) + (lane & 7);
    int a_cofs = wm + (((lane >> 3) & 1) << 3);
    int brow = lane & 15, bcol8 = (lane >> 4) << 3;

#pragma unroll
    for (int ks = 0; ks < 8; ks++) {
        uint32_t a[4];
        ldsm_x4_t(a, ksb + (uint32_t)((ks * 16 + a_rofs) * PA_STRIDE + a_cofs) * 2);
#pragma unroll
        for (int p = 0; p < 4; p++) {
            uint32_t r[4];
            ldsm_x4_t(r, vsb + (uint32_t)((ks * 16 + brow) * PA_STRIDE + p * 16 + bcol8) * 2);
            mma16816(cS[2 * p],     a, r[0], r[1]);
            mma16816(cS[2 * p + 1], a, r[2], r[3]);
        }
    }

    unsigned short* Sg = (unsigned short*)g_Sh + ((size_t)(bh * NCv + c)) * (HDv * HDv);
    int d0 = wm + (lane >> 2);
    int e0 = (lane & 3) * 2;
#pragma unroll
    for (int nb = 0; nb < 8; nb++) {
        *(uint32_t*)(Sg + d0 * 64 + nb * 8 + e0)       = pack_h2(cS[nb][0], cS[nb][1]);
        *(uint32_t*)(Sg + (d0 + 8) * 64 + nb * 8 + e0) = pack_h2(cS[nb][2], cS[nb][3]);
    }
}

// ---------------------------------------------------------------------------
// Phase B: register-resident exclusive prefix scan over fp16 S (fp32 run),
// MLP=32: all strided loads issued before the serial add chain.
// ---------------------------------------------------------------------------
__global__ __launch_bounds__(256)
void phaseB_kernel()
{
    int bh  = blockIdx.x;
    int grp = blockIdx.y;
    int t   = threadIdx.x;
    int idx = grp * 256 + t;

    __half* Sg = g_Sh + (size_t)bh * NCv * (HDv * HDv) + idx;
    __half v[NCv];
#pragma unroll
    for (int c = 0; c < NCv; c++) v[c] = Sg[c * (HDv * HDv)];
    float run = 0.f;
#pragma unroll
    for (int c = 0; c < NCv; c++) {
        float x = __half2float(v[c]);
        Sg[c * (HDv * HDv)] = __float2half_rn(run);
        run += x;
    }

    if (grp == 0 && t < HDv) {
        float* zg = g_z + (size_t)bh * NCv * HDv + t;
        float zv[NCv];
#pragma unroll
        for (int c = 0; c < NCv; c++) zv[c] = zg[c * HDv];
        float rz = 0.f;
#pragma unroll
        for (int c = 0; c < NCv; c++) {
            float x = zv[c];
            zg[c * HDv] = rz;
            rz += x;
        }
    }
}

// ---------------------------------------------------------------------------
// Phase C v2 (tensor, low register pressure): jb-outer P computation — each
// 16-column strip cPj[2][4] is computed, masked, folded into rowsums, packed
// into aP[jb], and released. Identical arithmetic order to v1 (ks ascending
// per element, nb ascending for rowsums) => bitwise-same output.
// __launch_bounds__(256, 2): 2 CTAs/SM so sync/load phases overlap cross-CTA.
// ---------------------------------------------------------------------------
#define QS_STRIDE 72
#define PHC_SMEM ((3 * 128 * QS_STRIDE + 64 * QS_STRIDE) * 2 + 64 * 4)

__global__ __launch_bounds__(256, 2)
void phaseC_kernel()
{
    extern __shared__ __half smc[];
    __half* Qs = smc;
    __half* Ks = smc + 128 * QS_STRIDE;
    __half* Vs = smc + 2 * 128 * QS_STRIDE;
    __half* Sh = smc + 3 * 128 * QS_STRIDE;
    float*  zf = (float*)(smc + 3 * 128 * QS_STRIDE + 64 * QS_STRIDE);

    int blk = blockIdx.x;
    int c   = blk & (NCv - 1);
    int bh  = blk >> 5;
    int h   = bh & (Hv - 1);
    int b   = bh >> 4;
    int t   = threadIdx.x;
    int lane = t & 31, wid = t >> 5;

    size_t base = ((size_t)(b * Tv + c * Cv)) * Dv + h * HDv;

    for (int idx = t; idx < 128 * 8; idx += 256) {
        int row = idx >> 3, c8 = (idx & 7) << 3;
        size_t go = base + (size_t)row * Dv + c8;
        uint32_t so = (uint32_t)(row * QS_STRIDE + c8);
        *(uint4*)&Qs[so] = *(const uint4*)((const unsigned short*)g_Qh + go);
        *(uint4*)&Ks[so] = *(const uint4*)((const unsigned short*)g_Kh + go);
        *(uint4*)&Vs[so] = *(const uint4*)((const unsigned short*)g_Vh + go);
    }
    const unsigned short* Sg =
        (const unsigned short*)g_Sh + ((size_t)(bh * NCv + c)) * (HDv * HDv);
    for (int idx = t; idx < 512; idx += 256) {
        int row = idx >> 3, c8 = (idx & 7) << 3;
        *(uint4*)&Sh[row * QS_STRIDE + c8] = *(const uint4*)(Sg + row * 64 + c8);
    }
    if (t < 64) zf[t] = g_z[(size_t)(bh * NCv + c) * HDv + t];
    __syncthreads();

    uint32_t qsb = smem_u32(Qs), ksb = smem_u32(Ks), vsb = smem_u32(Vs), shb = smem_u32(Sh);

    int i0 = wid * 16;
    int arow = lane & 15, acol8 = (lane >> 4) << 3;

    uint32_t aQ[4][4];
#pragma unroll
    for (int ks = 0; ks < 4; ks++)
        ldsm_x4(aQ[ks], qsb + (uint32_t)((i0 + arow) * QS_STRIDE + ks * 16 + acol8) * 2);

    int r0 = i0 + (lane >> 2);
    int cb = (lane & 3) * 2;

    // P stage, jb-outer: compute strip, mask, rowsum, pack, release.
    uint32_t aP[8][4];
    float rs0 = 0.f, rs1 = 0.f;
#pragma unroll
    for (int jb = 0; jb < 8; jb++) {
        float cPj[2][4];
#pragma unroll
        for (int hh = 0; hh < 2; hh++)
#pragma unroll
            for (int q = 0; q < 4; q++) cPj[hh][q] = 0.f;

#pragma unroll
        for (int ks = 0; ks < 4; ks++) {
            uint32_t r[4];
            ldsm_x4(r, ksb + (uint32_t)((jb * 16 + arow) * QS_STRIDE + ks * 16 + acol8) * 2);
            mma16816(cPj[0], aQ[ks], r[0], r[2]);   // cols jb*16 + 0..7
            mma16816(cPj[1], aQ[ks], r[1], r[3]);   // cols jb*16 + 8..15
        }

#pragma unroll
        for (int hh = 0; hh < 2; hh++) {
            int j0 = jb * 16 + hh * 8 + cb;
            if (j0     > r0)     cPj[hh][0] = 0.f;
            if (j0 + 1 > r0)     cPj[hh][1] = 0.f;
            if (j0     > r0 + 8) cPj[hh][2] = 0.f;
            if (j0 + 1 > r0 + 8) cPj[hh][3] = 0.f;
            rs0 += cPj[hh][0] + cPj[hh][1];
            rs1 += cPj[hh][2] + cPj[hh][3];
        }

        aP[jb][0] = pack_h2(cPj[0][0], cPj[0][1]);
        aP[jb][1] = pack_h2(cPj[0][2], cPj[0][3]);
        aP[jb][2] = pack_h2(cPj[1][0], cPj[1][1]);
        aP[jb][3] = pack_h2(cPj[1][2], cPj[1][3]);
    }

    rs0 += __shfl_xor_sync(0xffffffffu, rs0, 1);
    rs0 += __shfl_xor_sync(0xffffffffu, rs0, 2);
    rs1 += __shfl_xor_sync(0xffffffffu, rs1, 1);
    rs1 += __shfl_xor_sync(0xffffffffu, rs1, 2);

    float qz0 = 0.f, qz1 = 0.f;
    for (int d = 0; d < 64; d++) {
        float zz = zf[d];
        qz0 += __half2float(Qs[r0 * QS_STRIDE + d]) * zz;
        qz1 += __half2float(Qs[(r0 + 8) * QS_STRIDE + d]) * zz;
    }
    float inv0 = 1.f / (rs0 + qz0 + 1e-6f);
    float inv1 = 1.f / (rs1 + qz1 + 1e-6f);

    // O = P V + Q S_prev
    float cO[8][4];
#pragma unroll
    for (int nb = 0; nb < 8; nb++)
#pragma unroll
        for (int q = 0; q < 4; q++) cO[nb][q] = 0.f;

#pragma unroll
    for (int jk = 0; jk < 8; jk++) {
#pragma unroll
        for (int p = 0; p < 4; p++) {
            uint32_t r[4];
            ldsm_x4_t(r, vsb + (uint32_t)((jk * 16 + arow) * QS_STRIDE + p * 16 + acol8) * 2);
            mma16816(cO[2 * p],     aP[jk], r[0], r[1]);
            mma16816(cO[2 * p + 1], aP[jk], r[2], r[3]);
        }
    }
#pragma unroll
    for (int ks = 0; ks < 4; ks++) {
#pragma unroll
        for (int p = 0; p < 4; p++) {
            uint32_t r[4];
            ldsm_x4_t(r, shb + (uint32_t)((ks * 16 + arow) * QS_STRIDE + p * 16 + acol8) * 2);
            mma16816(cO[2 * p],     aQ[ks], r[0], r[1]);
            mma16816(cO[2 * p + 1], aQ[ks], r[2], r[3]);
        }
    }

    unsigned short* Yg = (unsigned short*)gA + base;
#pragma unroll
    for (int nb = 0; nb < 8; nb++) {
        int e = nb * 8 + cb;
        *(uint32_t*)(Yg + (size_t)r0 * Dv + e)       = pack_h2(cO[nb][0] * inv0, cO[nb][1] * inv0);
        *(uint32_t*)(Yg + (size_t)(r0 + 8) * Dv + e) = pack_h2(cO[nb][2] * inv1, cO[nb][3] * inv1);
    }
}

// ---------------------------------------------------------------------------
// Launch
// ---------------------------------------------------------------------------
extern "C" void kernel_launch(void* const* d_in, const int* in_sizes, int n_in,
                              void* d_out, int out_size)
{
    const float* x  = (const float*)d_in[0];
    const float* Wq = (const float*)d_in[1];
    const float* Wk = (const float*)d_in[2];
    const float* Wv = (const float*)d_in[3];
    const float* Wo = (const float*)d_in[4];
    float* out = (float*)d_out;

    cudaFuncSetAttribute(mma_gemm_kernel,
                         cudaFuncAttributeMaxDynamicSharedMemorySize, GEMM_SMEM);
    cudaFuncSetAttribute(phaseC_kernel,
                         cudaFuncAttributeMaxDynamicSharedMemorySize, PHC_SMEM);

    conv_kernel<<<CONV_BLOCKS, 256>>>(x, Wq, Wk, Wv, Wo);

    dim3 gqkv(1024 / 128, Mv / 128, 3);
    mma_gemm_kernel<<<gqkv, 128, GEMM_SMEM>>>(-1, nullptr, 0, 0);  // fp16 Q/K/V

    phaseA_kernel<<<Bv * Hv * NCv, 128>>>();
    dim3 gb(Bv * Hv, 16);
    phaseB_kernel<<<gb, 256>>>();
    phaseC_kernel<<<Bv * Hv * NCv, 256, PHC_SMEM>>>();             // fp16 Y into gA

    dim3 go(1024 / 128, Mv / 128);
    mma_gemm_kernel<<<go, 128, GEMM_SMEM>>>(3, out, 3, 0);         // out = Y@Wo
}